// round 7
// baseline (speedup 1.0000x reference)
#include <cuda_runtime.h>
#include <math.h>

// Problem constants
#define NTOKS 4096   // B*T
#define DIMV  512
#define QDV   2048   // 2*H*DH
#define HV    8
#define DHV   128
#define NKV   256
#define KKV   16

typedef unsigned long long ull;

// packed fp32x2 FMA (sm_103a FFMA2) — bit-exact fp32 per lane
#define FMA2(d, a, b) \
    asm("fma.rn.f32x2 %0, %1, %2, %0;" : "+l"(d) : "l"(a), "l"(b))
#define UNPACK2(lo, hi, in) \
    asm("mov.b64 {%0, %1}, %2;" : "=r"(lo), "=r"(hi) : "l"(in))

// Scratch (allocation-free rule: __device__ globals)
__device__ __align__(16) float g_q[NTOKS * QDV];          // projected then LN'd q
__device__ __align__(16) float g_attn[NTOKS * HV * KKV];  // softmax weights
__device__ __align__(16) int   g_vidx[NTOKS * HV * KKV];  // value row indices

// Stage-2 candidate tables: (i,j) with (i+1)(j+1) <= 16 — 50 candidates,
// provably a superset of the top-16 of sx[i]+sy[j] with sx,sy sorted desc
// (exact under the reference's lower-flattened-index tie-break).
__device__ __constant__ int c_ci[64] = {
    0,0,0,0,0,0,0,0,0,0,0,0,0,0,0,0,
    1,1,1,1,1,1,1,1,
    2,2,2,2,2,
    3,3,3,3,
    4,4,4,
    5,5, 6,6, 7,7,
    8,9,10,11,12,13,14,15,
    0,0,0,0,0,0,0,0,0,0,0,0,0,0};
__device__ __constant__ int c_cj[64] = {
    0,1,2,3,4,5,6,7,8,9,10,11,12,13,14,15,
    0,1,2,3,4,5,6,7,
    0,1,2,3,4,
    0,1,2,3,
    0,1,2,
    0,1, 0,1, 0,1,
    0,0,0,0,0,0,0,0,
    0,0,0,0,0,0,0,0,0,0,0,0,0,0};

// ---------------------------------------------------------------------------
// K1: q = x @ Wq^T  (M=4096, N=2048, K=512) with FFMA2 — identical FMA chain
// to round 6 (bit-exact). New: B stored pre-duplicated in smem (no PACKDUP
// MOVs) + register-prefetch software pipeline for the staging LDGs.
// ---------------------------------------------------------------------------
__global__ __launch_bounds__(256, 2) void k1_gemm(const float* __restrict__ X,
                                                  const float* __restrict__ W)
{
    __shared__ float As[16][132];   // [k][m]
    __shared__ float Bsd[16][260];  // [k][2n] duplicated pairs

    const int tid = threadIdx.x;
    const int tx = tid & 15;       // n-group
    const int ty = tid >> 4;       // m-group
    const int m0 = blockIdx.x * 128;
    const int n0 = blockIdx.y * 128;

    const int srow = tid >> 2;         // 0..63 (chunk-local staging row)
    const int skc  = (tid & 3) << 2;   // k offset 0,4,8,12

    ull acc[4][8];                 // [row-pair][col]
#pragma unroll
    for (int ip = 0; ip < 4; ip++)
#pragma unroll
        for (int j = 0; j < 8; j++) acc[ip][j] = 0ULL;

    // prologue: prefetch tile kt=0 into registers
    float4 pa[2], pb[2];
#pragma unroll
    for (int q = 0; q < 2; q++) {
        pa[q] = *(const float4*)(X + (size_t)(m0 + q * 64 + srow) * DIMV + skc);
        pb[q] = *(const float4*)(W + (size_t)(n0 + q * 64 + srow) * DIMV + skc);
    }

    for (int kt = 0; kt < DIMV; kt += 16) {
        // store staged registers to smem (A transposed, B transposed+duplicated)
#pragma unroll
        for (int q = 0; q < 2; q++) {
            int row = q * 64 + srow;
            As[skc + 0][row] = pa[q].x; As[skc + 1][row] = pa[q].y;
            As[skc + 2][row] = pa[q].z; As[skc + 3][row] = pa[q].w;
            *(float2*)&Bsd[skc + 0][2 * row] = make_float2(pb[q].x, pb[q].x);
            *(float2*)&Bsd[skc + 1][2 * row] = make_float2(pb[q].y, pb[q].y);
            *(float2*)&Bsd[skc + 2][2 * row] = make_float2(pb[q].z, pb[q].z);
            *(float2*)&Bsd[skc + 3][2 * row] = make_float2(pb[q].w, pb[q].w);
        }
        __syncthreads();
        // prefetch next tile (overlaps with the 16-k compute below)
        if (kt + 16 < DIMV) {
#pragma unroll
            for (int q = 0; q < 2; q++) {
                pa[q] = *(const float4*)(X + (size_t)(m0 + q * 64 + srow) * DIMV + kt + 16 + skc);
                pb[q] = *(const float4*)(W + (size_t)(n0 + q * 64 + srow) * DIMV + kt + 16 + skc);
            }
        }
#pragma unroll 4
        for (int k = 0; k < 16; k++) {
            ulonglong2 a01 = *(const ulonglong2*)&As[k][ty * 4];
            ulonglong2 a23 = *(const ulonglong2*)&As[k][64 + ty * 4];
            ull av[4] = {a01.x, a01.y, a23.x, a23.y};
            ulonglong2 b0 = *(const ulonglong2*)&Bsd[k][8 * tx];
            ulonglong2 b1 = *(const ulonglong2*)&Bsd[k][8 * tx + 4];
            ulonglong2 b2 = *(const ulonglong2*)&Bsd[k][128 + 8 * tx];
            ulonglong2 b3 = *(const ulonglong2*)&Bsd[k][128 + 8 * tx + 4];
            ull bd[8] = {b0.x, b0.y, b1.x, b1.y, b2.x, b2.y, b3.x, b3.y};
#pragma unroll
            for (int ip = 0; ip < 4; ip++)
#pragma unroll
                for (int j = 0; j < 8; j++)
                    FMA2(acc[ip][j], av[ip], bd[j]);
        }
        __syncthreads();
    }

    // raw store (LN done by k2, verbatim round-2 kernel, for bit-exactness)
#pragma unroll
    for (int ip = 0; ip < 4; ip++) {
#pragma unroll
        for (int e = 0; e < 2; e++) {
            int row = (ip >> 1) * 64 + ty * 4 + (ip & 1) * 2 + e;  // local m
            float o[8];
#pragma unroll
            for (int j = 0; j < 8; j++) {
                unsigned lo, hi;
                UNPACK2(lo, hi, acc[ip][j]);
                o[j] = __uint_as_float(e ? hi : lo);
            }
            float* dst = g_q + (size_t)(m0 + row) * QDV + n0;
            *(float4*)(dst + tx * 4)      = make_float4(o[0], o[1], o[2], o[3]);
            *(float4*)(dst + 64 + tx * 4) = make_float4(o[4], o[5], o[6], o[7]);
        }
    }
}

// ---------------------------------------------------------------------------
// K2: LayerNorm over each 128-elem subrow of g_q (in place). Warp per row.
// VERBATIM round-2 kernel (bit-exact reduction tree).
// ---------------------------------------------------------------------------
__global__ __launch_bounds__(256) void k2_ln(const float* __restrict__ gamma,
                                             const float* __restrict__ beta)
{
    int gw = (int)((blockIdx.x * blockDim.x + threadIdx.x) >> 5);  // 0..65535
    int lane = threadIdx.x & 31;
    float* row = g_q + (size_t)gw * DHV;

    float4 v = *(float4*)(row + lane * 4);
    float s = v.x + v.y + v.z + v.w;
#pragma unroll
    for (int o = 16; o; o >>= 1) s += __shfl_xor_sync(0xffffffffu, s, o);
    float mu = s * (1.0f / 128.0f);

    float dx = v.x - mu, dy = v.y - mu, dz = v.z - mu, dw = v.w - mu;
    float ss = dx * dx + dy * dy + dz * dz + dw * dw;
#pragma unroll
    for (int o = 16; o; o >>= 1) ss += __shfl_xor_sync(0xffffffffu, ss, o);
    float inv = rsqrtf(ss * (1.0f / 128.0f) + 1e-5f);

    float4 g4 = *(const float4*)(gamma + lane * 4);
    float4 b4 = *(const float4*)(beta + lane * 4);
    v.x = dx * inv * g4.x + b4.x;
    v.y = dy * inv * g4.y + b4.y;
    v.z = dz * inv * g4.z + b4.z;
    v.w = dw * inv * g4.w + b4.w;
    *(float4*)(row + lane * 4) = v;
}

// ---------------------------------------------------------------------------
// K3 (fused K4): dots + stage-1 top-16 + pruned stage-2 + softmax.
// Identical FMA order to round 6; q now stored pre-duplicated in smem
// (broadcast LDS.64 replaces PACKDUP's MOV pair).
// ---------------------------------------------------------------------------
__global__ __launch_bounds__(256) void k3_fused(const float* __restrict__ keys)
{
    __shared__ float qsd[32][66];  // [token][2k] duplicated pairs
    __shared__ float ks[32][256];  // [k][key] transposed

    const int tid = threadIdx.x;
    const int tx = tid & 31;
    const int wy = tid >> 5;       // warp id: token group
    const int tt = blockIdx.x;
    const int h = blockIdx.y;
    const int t0 = tt * 32;

    ull acc[2][4][4];              // [p][token][key-pair-quad]
#pragma unroll
    for (int p = 0; p < 2; p++)
#pragma unroll
        for (int i = 0; i < 4; i++)
#pragma unroll
            for (int jq = 0; jq < 4; jq++) acc[p][i][jq] = 0ULL;

    const int tl = tid >> 3;
    const int kc = (tid & 7) << 2;

    for (int p = 0; p < 2; p++) {
        const float* qb = g_q + (size_t)(p * HV + h) * DHV;
        const float* kb = keys + ((size_t)(h * NKV + tid) * 2 + p) * DHV;
        for (int kt = 0; kt < DHV; kt += 32) {
            __syncthreads();
            float4 q4 = *(const float4*)(qb + (size_t)(t0 + tl) * QDV + kt + kc);
            *(float2*)&qsd[tl][2 * (kc + 0)] = make_float2(q4.x, q4.x);
            *(float2*)&qsd[tl][2 * (kc + 1)] = make_float2(q4.y, q4.y);
            *(float2*)&qsd[tl][2 * (kc + 2)] = make_float2(q4.z, q4.z);
            *(float2*)&qsd[tl][2 * (kc + 3)] = make_float2(q4.w, q4.w);
            const float* kr = kb + kt;  // key row n = tid (256 keys)
#pragma unroll
            for (int c = 0; c < 8; c++) {
                float4 k4 = *(const float4*)(kr + c * 4);
                ks[c * 4 + 0][tid] = k4.x; ks[c * 4 + 1][tid] = k4.y;
                ks[c * 4 + 2][tid] = k4.z; ks[c * 4 + 3][tid] = k4.w;
            }
            __syncthreads();
#pragma unroll 4
            for (int k = 0; k < 32; k++) {
                ull kv[4];
#pragma unroll
                for (int jq = 0; jq < 4; jq++)
                    kv[jq] = *(const ull*)&ks[k][64 * jq + 2 * tx];
#pragma unroll
                for (int i = 0; i < 4; i++) {
                    ull qd = *(const ull*)&qsd[wy + 8 * i][2 * k];
#pragma unroll
                    for (int jq = 0; jq < 4; jq++)
                        FMA2(acc[p][i][jq], qd, kv[jq]);
                }
            }
        }
    }

    // selection per token
#pragma unroll 1
    for (int i = 0; i < 4; i++) {
        const int t = t0 + wy + 8 * i;
        float s1s[2];
        int s1i[2];
        // stage 1: top-16 of 256 per p (after: lane l<16 holds l-th best)
#pragma unroll 1
        for (int p = 0; p < 2; p++) {
            float v[8];
#pragma unroll
            for (int jq = 0; jq < 4; jq++) {
                unsigned lo, hi;
                UNPACK2(lo, hi, acc[p][i][jq]);
                v[2 * jq + 0] = __uint_as_float(lo);
                v[2 * jq + 1] = __uint_as_float(hi);
            }
            float os = 0.f; int oi = 0;
#pragma unroll 1
            for (int it = 0; it < 16; it++) {
                float bv = -INFINITY; int bi = 0x7fffffff;
#pragma unroll
                for (int s = 0; s < 8; s++) {
                    int n = ((s >> 1) << 6) + 2 * tx + (s & 1);
                    if (v[s] > bv) { bv = v[s]; bi = n; }
                }
#pragma unroll
                for (int o = 16; o; o >>= 1) {
                    float ov = __shfl_xor_sync(0xffffffffu, bv, o);
                    int oi2 = __shfl_xor_sync(0xffffffffu, bi, o);
                    if (ov > bv || (ov == bv && oi2 < bi)) { bv = ov; bi = oi2; }
                }
                if (tx == it) { os = bv; oi = bi; }
                if (((bi >> 1) & 31) == tx) {
                    int sl = ((bi >> 6) << 1) | (bi & 1);
                    v[sl] = -INFINITY;
                }
            }
            s1s[p] = os; s1i[p] = oi;
        }

        // stage 2: top-16 of 50 pruned candidates (lane l: c=l and c=l+32)
        float v2[2]; int cc2[2];
#pragma unroll
        for (int e = 0; e < 2; e++) {
            int c = tx + 32 * e;
            int ii = c_ci[c], jj = c_cj[c];
            float sxv = __shfl_sync(0xffffffffu, s1s[0], ii);
            float syv = __shfl_sync(0xffffffffu, s1s[1], jj);
            v2[e] = (c < 50) ? sxv + syv : -INFINITY;
            cc2[e] = ii * 16 + jj;
        }
        float os = 0.f; int occ = 0;
#pragma unroll 1
        for (int it = 0; it < 16; it++) {
            float bv = -INFINITY; int bcc = 0x7fffffff;
#pragma unroll
            for (int e = 0; e < 2; e++)
                if (v2[e] > bv || (v2[e] == bv && cc2[e] < bcc)) { bv = v2[e]; bcc = cc2[e]; }
#pragma unroll
            for (int o = 16; o; o >>= 1) {
                float ov = __shfl_xor_sync(0xffffffffu, bv, o);
                int oc2 = __shfl_xor_sync(0xffffffffu, bcc, o);
                if (ov > bv || (ov == bv && oc2 < bcc)) { bv = ov; bcc = oc2; }
            }
            if (tx == it) { os = bv; occ = bcc; }
#pragma unroll
            for (int e = 0; e < 2; e++)
                if (cc2[e] == bcc) v2[e] = -INFINITY;
        }

        // softmax over 16 selected (lane 0 = max) + index gather
        float mx = __shfl_sync(0xffffffffu, os, 0);
        float ev = (tx < 16) ? expf(os - mx) : 0.f;
        float sum = ev;
#pragma unroll
        for (int o = 16; o; o >>= 1) sum += __shfl_xor_sync(0xffffffffu, sum, o);
        int ix = __shfl_sync(0xffffffffu, s1i[0], (occ >> 4) & 15);
        int iy = __shfl_sync(0xffffffffu, s1i[1], occ & 15);
        if (tx < 16) {
            int o = (t * HV + h) * KKV + tx;
            g_attn[o] = ev / sum;
            g_vidx[o] = ix * NKV + iy;
        }
    }
}

// ---------------------------------------------------------------------------
// K5: out[t,:] = sum_{m<128} attn[t,m] * values[vidx[t,m], :]
// (at DRAM/L2 bandwidth floor per ncu — unchanged)
// ---------------------------------------------------------------------------
__global__ __launch_bounds__(128) void k5_out(const float* __restrict__ values,
                                              float* __restrict__ out)
{
    __shared__ float sa[128];
    __shared__ int   sv[128];
    const int t = blockIdx.x;
    const int tid = threadIdx.x;
    sa[tid] = g_attn[(size_t)t * 128 + tid];
    sv[tid] = g_vidx[(size_t)t * 128 + tid];
    __syncthreads();

    const float4* V = (const float4*)values;
    float4 acc = make_float4(0.f, 0.f, 0.f, 0.f);
#pragma unroll 8
    for (int m = 0; m < 128; m++) {
        float a = sa[m];
        float4 vv = V[(size_t)sv[m] * 128 + tid];
        acc.x = fmaf(a, vv.x, acc.x);
        acc.y = fmaf(a, vv.y, acc.y);
        acc.z = fmaf(a, vv.z, acc.z);
        acc.w = fmaf(a, vv.w, acc.w);
    }
    ((float4*)out)[(size_t)t * 128 + tid] = acc;
}

// ---------------------------------------------------------------------------
extern "C" void kernel_launch(void* const* d_in, const int* in_sizes, int n_in,
                              void* d_out, int out_size)
{
    const float* x      = (const float*)d_in[0];  // (4,1024,512)
    const float* Wq     = (const float*)d_in[1];  // (2048,512)
    const float* ln_g   = (const float*)d_in[2];  // (128,)
    const float* ln_b   = (const float*)d_in[3];  // (128,)
    const float* keys   = (const float*)d_in[4];  // (8,256,2,128)
    const float* values = (const float*)d_in[5];  // (65536,512)
    float* out = (float*)d_out;                   // (4,1024,512)

    k1_gemm<<<dim3(NTOKS / 128, QDV / 128), 256>>>(x, Wq);
    k2_ln<<<(NTOKS * 16) / 8, 256>>>(ln_g, ln_b);
    k3_fused<<<dim3(NTOKS / 32, HV), 256>>>(keys);
    k5_out<<<NTOKS, 128>>>(values, out);
}

// round 8
// speedup vs baseline: 1.2317x; 1.2317x over previous
#include <cuda_runtime.h>
#include <math.h>

// Problem constants
#define NTOKS 4096   // B*T
#define DIMV  512
#define QDV   2048   // 2*H*DH
#define HV    8
#define DHV   128
#define NKV   256
#define KKV   16

typedef unsigned long long ull;

// packed fp32x2 FMA (sm_103a FFMA2) — bit-exact fp32 per lane
#define FMA2(d, a, b) \
    asm("fma.rn.f32x2 %0, %1, %2, %0;" : "+l"(d) : "l"(a), "l"(b))
#define PACKDUP(out, x) \
    asm("mov.b64 %0, {%1, %1};" : "=l"(out) : "r"(__float_as_uint(x)))
#define UNPACK2(lo, hi, in) \
    asm("mov.b64 {%0, %1}, %2;" : "=r"(lo), "=r"(hi) : "l"(in))

// Scratch (allocation-free rule: __device__ globals)
__device__ __align__(16) float g_q[NTOKS * QDV];          // projected then LN'd q
__device__ __align__(16) float g_attn[NTOKS * HV * KKV];  // softmax weights
__device__ __align__(16) int   g_vidx[NTOKS * HV * KKV];  // value row indices

// Stage-2 candidate tables: (i,j) with (i+1)(j+1) <= 16 — 50 candidates,
// provably a superset of the top-16 of sx[i]+sy[j] with sx,sy sorted desc
// (exact under the reference's lower-flattened-index tie-break).
__device__ __constant__ int c_ci[64] = {
    0,0,0,0,0,0,0,0,0,0,0,0,0,0,0,0,
    1,1,1,1,1,1,1,1,
    2,2,2,2,2,
    3,3,3,3,
    4,4,4,
    5,5, 6,6, 7,7,
    8,9,10,11,12,13,14,15,
    0,0,0,0,0,0,0,0,0,0,0,0,0,0};
__device__ __constant__ int c_cj[64] = {
    0,1,2,3,4,5,6,7,8,9,10,11,12,13,14,15,
    0,1,2,3,4,5,6,7,
    0,1,2,3,4,
    0,1,2,3,
    0,1,2,
    0,1, 0,1, 0,1,
    0,0,0,0,0,0,0,0,
    0,0,0,0,0,0,0,0,0,0,0,0,0,0};

// ---------------------------------------------------------------------------
// K1: q = x @ Wq^T  (M=4096, N=2048, K=512), FFMA2, bit-exact sequential-k
// chain per output. Re-tiled: 64x128 block tile, 256 threads, 8m x 4n per
// thread (16 ull accumulators -> ~3 CTAs/SM for stall hiding). a-loads are
// warp-broadcast; b-loads 16B-stride conflict-free.
// ---------------------------------------------------------------------------
__global__ __launch_bounds__(256) void k1_gemm(const float* __restrict__ X,
                                               const float* __restrict__ W)
{
    __shared__ float As[16][68];    // [k][m] 64 rows + pad
    __shared__ float Bs[16][132];   // [k][n] 128 rows + pad

    const int tid = threadIdx.x;
    const int tx = tid & 31;       // n-group: cols tx*4..tx*4+3
    const int ty = tid >> 5;       // m-group (warp id): rows ty*4+{0..3}, +32
    const int m0 = blockIdx.x * 64;
    const int n0 = blockIdx.y * 128;

    ull acc[4][4];                 // [row-pair][col]
#pragma unroll
    for (int ip = 0; ip < 4; ip++)
#pragma unroll
        for (int j = 0; j < 4; j++) acc[ip][j] = 0ULL;

    const int arow = tid >> 2;          // 0..63
    const int akc  = (tid & 3) << 2;    // 0,4,8,12

    for (int kt = 0; kt < DIMV; kt += 16) {
        // stage A: 64 rows x 16 k (1 float4/thread), transposed
        float4 a4 = *(const float4*)(X + (size_t)(m0 + arow) * DIMV + kt + akc);
        As[akc + 0][arow] = a4.x; As[akc + 1][arow] = a4.y;
        As[akc + 2][arow] = a4.z; As[akc + 3][arow] = a4.w;
        // stage B: 128 rows x 16 k (2 float4/thread), transposed
#pragma unroll
        for (int q = 0; q < 2; q++) {
            int idx = q * 256 + tid;
            int brow = idx >> 2;
            int bkc = (idx & 3) << 2;
            float4 b4 = *(const float4*)(W + (size_t)(n0 + brow) * DIMV + kt + bkc);
            Bs[bkc + 0][brow] = b4.x; Bs[bkc + 1][brow] = b4.y;
            Bs[bkc + 2][brow] = b4.z; Bs[bkc + 3][brow] = b4.w;
        }
        __syncthreads();
#pragma unroll 4
        for (int k = 0; k < 16; k++) {
            // a: rows ty*4+{0,1},{2,3} and 32+ty*4+{0,1},{2,3} (warp-broadcast)
            ulonglong2 a01 = *(const ulonglong2*)&As[k][ty * 4];
            ulonglong2 a23 = *(const ulonglong2*)&As[k][32 + ty * 4];
            ull av[4] = {a01.x, a01.y, a23.x, a23.y};
            // b: 4 scalars, duplicated into pairs
            float4 b = *(const float4*)&Bs[k][tx * 4];
            ull bd[4];
            PACKDUP(bd[0], b.x); PACKDUP(bd[1], b.y);
            PACKDUP(bd[2], b.z); PACKDUP(bd[3], b.w);
#pragma unroll
            for (int ip = 0; ip < 4; ip++)
#pragma unroll
                for (int j = 0; j < 4; j++)
                    FMA2(acc[ip][j], av[ip], bd[j]);
        }
        __syncthreads();
    }

    // store: row = (ip>>1)*32 + ty*4 + (ip&1)*2 + e, cols n0 + tx*4 + j
#pragma unroll
    for (int ip = 0; ip < 4; ip++) {
#pragma unroll
        for (int e = 0; e < 2; e++) {
            int row = (ip >> 1) * 32 + ty * 4 + (ip & 1) * 2 + e;
            float o[4];
#pragma unroll
            for (int j = 0; j < 4; j++) {
                unsigned lo, hi;
                UNPACK2(lo, hi, acc[ip][j]);
                o[j] = __uint_as_float(e ? hi : lo);
            }
            float* dst = g_q + (size_t)(m0 + row) * QDV + n0 + tx * 4;
            *(float4*)dst = make_float4(o[0], o[1], o[2], o[3]);
        }
    }
}

// ---------------------------------------------------------------------------
// K2: LayerNorm over each 128-elem subrow of g_q (in place). Warp per row.
// VERBATIM round-2 kernel (bit-exact reduction tree).
// ---------------------------------------------------------------------------
__global__ __launch_bounds__(256) void k2_ln(const float* __restrict__ gamma,
                                             const float* __restrict__ beta)
{
    int gw = (int)((blockIdx.x * blockDim.x + threadIdx.x) >> 5);  // 0..65535
    int lane = threadIdx.x & 31;
    float* row = g_q + (size_t)gw * DHV;

    float4 v = *(float4*)(row + lane * 4);
    float s = v.x + v.y + v.z + v.w;
#pragma unroll
    for (int o = 16; o; o >>= 1) s += __shfl_xor_sync(0xffffffffu, s, o);
    float mu = s * (1.0f / 128.0f);

    float dx = v.x - mu, dy = v.y - mu, dz = v.z - mu, dw = v.w - mu;
    float ss = dx * dx + dy * dy + dz * dz + dw * dw;
#pragma unroll
    for (int o = 16; o; o >>= 1) ss += __shfl_xor_sync(0xffffffffu, ss, o);
    float inv = rsqrtf(ss * (1.0f / 128.0f) + 1e-5f);

    float4 g4 = *(const float4*)(gamma + lane * 4);
    float4 b4 = *(const float4*)(beta + lane * 4);
    v.x = dx * inv * g4.x + b4.x;
    v.y = dy * inv * g4.y + b4.y;
    v.z = dz * inv * g4.z + b4.z;
    v.w = dw * inv * g4.w + b4.w;
    *(float4*)(row + lane * 4) = v;
}

// ---------------------------------------------------------------------------
// K3 (fused K4): VERBATIM from the 627.5us kernel. Dots (FFMA2, bit-exact
// k-order) + stage-1 top-16 per p + pruned stage-2 (50 cands) + softmax.
// ---------------------------------------------------------------------------
__global__ __launch_bounds__(256) void k3_fused(const float* __restrict__ keys)
{
    __shared__ float qs[32][33];   // [token][k]
    __shared__ float ks[32][256];  // [k][key] transposed

    const int tid = threadIdx.x;
    const int tx = tid & 31;
    const int wy = tid >> 5;       // warp id: token group
    const int tt = blockIdx.x;
    const int h = blockIdx.y;
    const int t0 = tt * 32;

    ull acc[2][4][4];              // [p][token][key-pair-quad]
#pragma unroll
    for (int p = 0; p < 2; p++)
#pragma unroll
        for (int i = 0; i < 4; i++)
#pragma unroll
            for (int jq = 0; jq < 4; jq++) acc[p][i][jq] = 0ULL;

    const int tl = tid >> 3;
    const int kc = (tid & 7) << 2;

    for (int p = 0; p < 2; p++) {
        const float* qb = g_q + (size_t)(p * HV + h) * DHV;
        const float* kb = keys + ((size_t)(h * NKV + tid) * 2 + p) * DHV;
        for (int kt = 0; kt < DHV; kt += 32) {
            __syncthreads();
            float4 q4 = *(const float4*)(qb + (size_t)(t0 + tl) * QDV + kt + kc);
            qs[tl][kc + 0] = q4.x; qs[tl][kc + 1] = q4.y;
            qs[tl][kc + 2] = q4.z; qs[tl][kc + 3] = q4.w;
            const float* kr = kb + kt;  // key row n = tid (256 keys)
#pragma unroll
            for (int c = 0; c < 8; c++) {
                float4 k4 = *(const float4*)(kr + c * 4);
                ks[c * 4 + 0][tid] = k4.x; ks[c * 4 + 1][tid] = k4.y;
                ks[c * 4 + 2][tid] = k4.z; ks[c * 4 + 3][tid] = k4.w;
            }
            __syncthreads();
#pragma unroll 4
            for (int k = 0; k < 32; k++) {
                ull kv[4];
#pragma unroll
                for (int jq = 0; jq < 4; jq++)
                    kv[jq] = *(const ull*)&ks[k][64 * jq + 2 * tx];
#pragma unroll
                for (int i = 0; i < 4; i++) {
                    ull qd;
                    PACKDUP(qd, qs[wy + 8 * i][k]);
#pragma unroll
                    for (int jq = 0; jq < 4; jq++)
                        FMA2(acc[p][i][jq], qd, kv[jq]);
                }
            }
        }
    }

    // selection per token
#pragma unroll 1
    for (int i = 0; i < 4; i++) {
        const int t = t0 + wy + 8 * i;
        float s1s[2];
        int s1i[2];
        // stage 1: top-16 of 256 per p (after: lane l<16 holds l-th best)
#pragma unroll 1
        for (int p = 0; p < 2; p++) {
            float v[8];
#pragma unroll
            for (int jq = 0; jq < 4; jq++) {
                unsigned lo, hi;
                UNPACK2(lo, hi, acc[p][i][jq]);
                v[2 * jq + 0] = __uint_as_float(lo);
                v[2 * jq + 1] = __uint_as_float(hi);
            }
            float os = 0.f; int oi = 0;
#pragma unroll 1
            for (int it = 0; it < 16; it++) {
                float bv = -INFINITY; int bi = 0x7fffffff;
#pragma unroll
                for (int s = 0; s < 8; s++) {
                    int n = ((s >> 1) << 6) + 2 * tx + (s & 1);
                    if (v[s] > bv) { bv = v[s]; bi = n; }
                }
#pragma unroll
                for (int o = 16; o; o >>= 1) {
                    float ov = __shfl_xor_sync(0xffffffffu, bv, o);
                    int oi2 = __shfl_xor_sync(0xffffffffu, bi, o);
                    if (ov > bv || (ov == bv && oi2 < bi)) { bv = ov; bi = oi2; }
                }
                if (tx == it) { os = bv; oi = bi; }
                if (((bi >> 1) & 31) == tx) {
                    int sl = ((bi >> 6) << 1) | (bi & 1);
                    v[sl] = -INFINITY;
                }
            }
            s1s[p] = os; s1i[p] = oi;
        }

        // stage 2: top-16 of 50 pruned candidates (lane l: c=l and c=l+32)
        float v2[2]; int cc2[2];
#pragma unroll
        for (int e = 0; e < 2; e++) {
            int c = tx + 32 * e;
            int ii = c_ci[c], jj = c_cj[c];
            float sxv = __shfl_sync(0xffffffffu, s1s[0], ii);
            float syv = __shfl_sync(0xffffffffu, s1s[1], jj);
            v2[e] = (c < 50) ? sxv + syv : -INFINITY;
            cc2[e] = ii * 16 + jj;
        }
        float os = 0.f; int occ = 0;
#pragma unroll 1
        for (int it = 0; it < 16; it++) {
            float bv = -INFINITY; int bcc = 0x7fffffff;
#pragma unroll
            for (int e = 0; e < 2; e++)
                if (v2[e] > bv || (v2[e] == bv && cc2[e] < bcc)) { bv = v2[e]; bcc = cc2[e]; }
#pragma unroll
            for (int o = 16; o; o >>= 1) {
                float ov = __shfl_xor_sync(0xffffffffu, bv, o);
                int oc2 = __shfl_xor_sync(0xffffffffu, bcc, o);
                if (ov > bv || (ov == bv && oc2 < bcc)) { bv = ov; bcc = oc2; }
            }
            if (tx == it) { os = bv; occ = bcc; }
#pragma unroll
            for (int e = 0; e < 2; e++)
                if (cc2[e] == bcc) v2[e] = -INFINITY;
        }

        // softmax over 16 selected (lane 0 = max) + index gather
        float mx = __shfl_sync(0xffffffffu, os, 0);
        float ev = (tx < 16) ? expf(os - mx) : 0.f;
        float sum = ev;
#pragma unroll
        for (int o = 16; o; o >>= 1) sum += __shfl_xor_sync(0xffffffffu, sum, o);
        int ix = __shfl_sync(0xffffffffu, s1i[0], (occ >> 4) & 15);
        int iy = __shfl_sync(0xffffffffu, s1i[1], occ & 15);
        if (tx < 16) {
            int o = (t * HV + h) * KKV + tx;
            g_attn[o] = ev / sum;
            g_vidx[o] = ix * NKV + iy;
        }
    }
}

// ---------------------------------------------------------------------------
// K5: out[t,:] = sum_{m<128} attn[t,m] * values[vidx[t,m], :]
// (at DRAM/L2 bandwidth floor per ncu — unchanged)
// ---------------------------------------------------------------------------
__global__ __launch_bounds__(128) void k5_out(const float* __restrict__ values,
                                              float* __restrict__ out)
{
    __shared__ float sa[128];
    __shared__ int   sv[128];
    const int t = blockIdx.x;
    const int tid = threadIdx.x;
    sa[tid] = g_attn[(size_t)t * 128 + tid];
    sv[tid] = g_vidx[(size_t)t * 128 + tid];
    __syncthreads();

    const float4* V = (const float4*)values;
    float4 acc = make_float4(0.f, 0.f, 0.f, 0.f);
#pragma unroll 8
    for (int m = 0; m < 128; m++) {
        float a = sa[m];
        float4 vv = V[(size_t)sv[m] * 128 + tid];
        acc.x = fmaf(a, vv.x, acc.x);
        acc.y = fmaf(a, vv.y, acc.y);
        acc.z = fmaf(a, vv.z, acc.z);
        acc.w = fmaf(a, vv.w, acc.w);
    }
    ((float4*)out)[(size_t)t * 128 + tid] = acc;
}

// ---------------------------------------------------------------------------
extern "C" void kernel_launch(void* const* d_in, const int* in_sizes, int n_in,
                              void* d_out, int out_size)
{
    const float* x      = (const float*)d_in[0];  // (4,1024,512)
    const float* Wq     = (const float*)d_in[1];  // (2048,512)
    const float* ln_g   = (const float*)d_in[2];  // (128,)
    const float* ln_b   = (const float*)d_in[3];  // (128,)
    const float* keys   = (const float*)d_in[4];  // (8,256,2,128)
    const float* values = (const float*)d_in[5];  // (65536,512)
    float* out = (float*)d_out;                   // (4,1024,512)

    k1_gemm<<<dim3(NTOKS / 64, QDV / 128), 256>>>(x, Wq);
    k2_ln<<<(NTOKS * 16) / 8, 256>>>(ln_g, ln_b);
    k3_fused<<<dim3(NTOKS / 32, HV), 256>>>(keys);
    k5_out<<<NTOKS, 128>>>(values, out);
}

// round 9
// speedup vs baseline: 1.3144x; 1.0671x over previous
#include <cuda_runtime.h>
#include <math.h>

// Problem constants
#define NTOKS 4096   // B*T
#define DIMV  512
#define QDV   2048   // 2*H*DH
#define HV    8
#define DHV   128
#define NKV   256
#define KKV   16

typedef unsigned long long ull;

// packed fp32x2 FMA (sm_103a FFMA2) — bit-exact fp32 per lane
#define FMA2(d, a, b) \
    asm("fma.rn.f32x2 %0, %1, %2, %0;" : "+l"(d) : "l"(a), "l"(b))
#define PACKDUP(out, x) \
    asm("mov.b64 %0, {%1, %1};" : "=l"(out) : "r"(__float_as_uint(x)))
#define UNPACK2(lo, hi, in) \
    asm("mov.b64 {%0, %1}, %2;" : "=r"(lo), "=r"(hi) : "l"(in))

// Scratch (allocation-free rule: __device__ globals)
__device__ __align__(16) float g_q[NTOKS * QDV];          // projected then LN'd q
__device__ __align__(16) float g_attn[NTOKS * HV * KKV];  // softmax weights
__device__ __align__(16) int   g_vidx[NTOKS * HV * KKV];  // value row indices

// Stage-2 candidate tables: (i,j) with (i+1)(j+1) <= 16 — 50 candidates,
// provably a superset of the top-16 of sx[i]+sy[j] with sx,sy sorted desc
// (exact under the reference's lower-flattened-index tie-break).
__device__ __constant__ int c_ci[64] = {
    0,0,0,0,0,0,0,0,0,0,0,0,0,0,0,0,
    1,1,1,1,1,1,1,1,
    2,2,2,2,2,
    3,3,3,3,
    4,4,4,
    5,5, 6,6, 7,7,
    8,9,10,11,12,13,14,15,
    0,0,0,0,0,0,0,0,0,0,0,0,0,0};
__device__ __constant__ int c_cj[64] = {
    0,1,2,3,4,5,6,7,8,9,10,11,12,13,14,15,
    0,1,2,3,4,5,6,7,
    0,1,2,3,4,
    0,1,2,3,
    0,1,2,
    0,1, 0,1, 0,1,
    0,0,0,0,0,0,0,0,
    0,0,0,0,0,0,0,0,0,0,0,0,0,0};

// ---------------------------------------------------------------------------
// K1: q = x @ Wq^T  (M=4096, N=2048, K=512), FFMA2, bit-exact sequential-k
// chain per output (identical to round 8). New: register-prefetch pipeline —
// next tile's LDGs issue right after the barrier and retire under the 16-k
// compute block, removing the exposed L2/DRAM latency per tile.
// ---------------------------------------------------------------------------
__global__ __launch_bounds__(256) void k1_gemm(const float* __restrict__ X,
                                               const float* __restrict__ W)
{
    __shared__ float As[16][68];    // [k][m] 64 rows + pad
    __shared__ float Bs[16][132];   // [k][n] 128 rows + pad

    const int tid = threadIdx.x;
    const int tx = tid & 31;       // n-group: cols tx*4..tx*4+3
    const int ty = tid >> 5;       // m-group (warp id)
    const int m0 = blockIdx.x * 64;
    const int n0 = blockIdx.y * 128;

    ull acc[4][4];                 // [row-pair][col]
#pragma unroll
    for (int ip = 0; ip < 4; ip++)
#pragma unroll
        for (int j = 0; j < 4; j++) acc[ip][j] = 0ULL;

    const int arow = tid >> 2;          // 0..63
    const int akc  = (tid & 3) << 2;    // 0,4,8,12
    const int brow0 = tid >> 2;         // 0..63   (q=0)
    const int brow1 = 64 + (tid >> 2);  // 64..127 (q=1)

    const float* Abase = X + (size_t)(m0 + arow) * DIMV + akc;
    const float* Bbase0 = W + (size_t)(n0 + brow0) * DIMV + akc;
    const float* Bbase1 = W + (size_t)(n0 + brow1) * DIMV + akc;

    // prologue: prefetch tile kt=0
    float4 pa  = *(const float4*)(Abase);
    float4 pb0 = *(const float4*)(Bbase0);
    float4 pb1 = *(const float4*)(Bbase1);

    for (int kt = 0; kt < DIMV; kt += 16) {
        // store staged registers to smem (transposed)
        As[akc + 0][arow] = pa.x; As[akc + 1][arow] = pa.y;
        As[akc + 2][arow] = pa.z; As[akc + 3][arow] = pa.w;
        Bs[akc + 0][brow0] = pb0.x; Bs[akc + 1][brow0] = pb0.y;
        Bs[akc + 2][brow0] = pb0.z; Bs[akc + 3][brow0] = pb0.w;
        Bs[akc + 0][brow1] = pb1.x; Bs[akc + 1][brow1] = pb1.y;
        Bs[akc + 2][brow1] = pb1.z; Bs[akc + 3][brow1] = pb1.w;
        __syncthreads();

        // prefetch next tile — retires under the compute below
        if (kt + 16 < DIMV) {
            pa  = *(const float4*)(Abase + kt + 16);
            pb0 = *(const float4*)(Bbase0 + kt + 16);
            pb1 = *(const float4*)(Bbase1 + kt + 16);
        }

#pragma unroll 4
        for (int k = 0; k < 16; k++) {
            ulonglong2 a01 = *(const ulonglong2*)&As[k][ty * 4];
            ulonglong2 a23 = *(const ulonglong2*)&As[k][32 + ty * 4];
            ull av[4] = {a01.x, a01.y, a23.x, a23.y};
            float4 b = *(const float4*)&Bs[k][tx * 4];
            ull bd[4];
            PACKDUP(bd[0], b.x); PACKDUP(bd[1], b.y);
            PACKDUP(bd[2], b.z); PACKDUP(bd[3], b.w);
#pragma unroll
            for (int ip = 0; ip < 4; ip++)
#pragma unroll
                for (int j = 0; j < 4; j++)
                    FMA2(acc[ip][j], av[ip], bd[j]);
        }
        __syncthreads();
    }

    // store: row = (ip>>1)*32 + ty*4 + (ip&1)*2 + e, cols n0 + tx*4 + j
#pragma unroll
    for (int ip = 0; ip < 4; ip++) {
#pragma unroll
        for (int e = 0; e < 2; e++) {
            int row = (ip >> 1) * 32 + ty * 4 + (ip & 1) * 2 + e;
            float o[4];
#pragma unroll
            for (int j = 0; j < 4; j++) {
                unsigned lo, hi;
                UNPACK2(lo, hi, acc[ip][j]);
                o[j] = __uint_as_float(e ? hi : lo);
            }
            float* dst = g_q + (size_t)(m0 + row) * QDV + n0 + tx * 4;
            *(float4*)dst = make_float4(o[0], o[1], o[2], o[3]);
        }
    }
}

// ---------------------------------------------------------------------------
// K2: LayerNorm over each 128-elem subrow of g_q (in place). Warp per row.
// VERBATIM round-2 kernel (bit-exact reduction tree).
// ---------------------------------------------------------------------------
__global__ __launch_bounds__(256) void k2_ln(const float* __restrict__ gamma,
                                             const float* __restrict__ beta)
{
    int gw = (int)((blockIdx.x * blockDim.x + threadIdx.x) >> 5);  // 0..65535
    int lane = threadIdx.x & 31;
    float* row = g_q + (size_t)gw * DHV;

    float4 v = *(float4*)(row + lane * 4);
    float s = v.x + v.y + v.z + v.w;
#pragma unroll
    for (int o = 16; o; o >>= 1) s += __shfl_xor_sync(0xffffffffu, s, o);
    float mu = s * (1.0f / 128.0f);

    float dx = v.x - mu, dy = v.y - mu, dz = v.z - mu, dw = v.w - mu;
    float ss = dx * dx + dy * dy + dz * dz + dw * dw;
#pragma unroll
    for (int o = 16; o; o >>= 1) ss += __shfl_xor_sync(0xffffffffu, ss, o);
    float inv = rsqrtf(ss * (1.0f / 128.0f) + 1e-5f);

    float4 g4 = *(const float4*)(gamma + lane * 4);
    float4 b4 = *(const float4*)(beta + lane * 4);
    v.x = dx * inv * g4.x + b4.x;
    v.y = dy * inv * g4.y + b4.y;
    v.z = dz * inv * g4.z + b4.z;
    v.w = dw * inv * g4.w + b4.w;
    *(float4*)(row + lane * 4) = v;
}

// ---------------------------------------------------------------------------
// K3 (fused K4): dots (FFMA2, bit-exact k-order, identical to round 8) +
// stage-1 top-16 with the two p-problems INTERLEAVED (ILP-2 over the
// dependent shuffle chains — same ops per problem, same tie-breaks) +
// pruned stage-2 (50 cands) + softmax.
// ---------------------------------------------------------------------------
__global__ __launch_bounds__(256) void k3_fused(const float* __restrict__ keys)
{
    __shared__ float qs[32][33];   // [token][k]
    __shared__ float ks[32][256];  // [k][key] transposed

    const int tid = threadIdx.x;
    const int tx = tid & 31;
    const int wy = tid >> 5;       // warp id: token group
    const int tt = blockIdx.x;
    const int h = blockIdx.y;
    const int t0 = tt * 32;

    ull acc[2][4][4];              // [p][token][key-pair-quad]
#pragma unroll
    for (int p = 0; p < 2; p++)
#pragma unroll
        for (int i = 0; i < 4; i++)
#pragma unroll
            for (int jq = 0; jq < 4; jq++) acc[p][i][jq] = 0ULL;

    const int tl = tid >> 3;
    const int kc = (tid & 7) << 2;

    for (int p = 0; p < 2; p++) {
        const float* qb = g_q + (size_t)(p * HV + h) * DHV;
        const float* kb = keys + ((size_t)(h * NKV + tid) * 2 + p) * DHV;
        for (int kt = 0; kt < DHV; kt += 32) {
            __syncthreads();
            float4 q4 = *(const float4*)(qb + (size_t)(t0 + tl) * QDV + kt + kc);
            qs[tl][kc + 0] = q4.x; qs[tl][kc + 1] = q4.y;
            qs[tl][kc + 2] = q4.z; qs[tl][kc + 3] = q4.w;
            const float* kr = kb + kt;  // key row n = tid (256 keys)
#pragma unroll
            for (int c = 0; c < 8; c++) {
                float4 k4 = *(const float4*)(kr + c * 4);
                ks[c * 4 + 0][tid] = k4.x; ks[c * 4 + 1][tid] = k4.y;
                ks[c * 4 + 2][tid] = k4.z; ks[c * 4 + 3][tid] = k4.w;
            }
            __syncthreads();
#pragma unroll 4
            for (int k = 0; k < 32; k++) {
                ull kv[4];
#pragma unroll
                for (int jq = 0; jq < 4; jq++)
                    kv[jq] = *(const ull*)&ks[k][64 * jq + 2 * tx];
#pragma unroll
                for (int i = 0; i < 4; i++) {
                    ull qd;
                    PACKDUP(qd, qs[wy + 8 * i][k]);
#pragma unroll
                    for (int jq = 0; jq < 4; jq++)
                        FMA2(acc[p][i][jq], qd, kv[jq]);
                }
            }
        }
    }

    // selection per token
#pragma unroll 1
    for (int i = 0; i < 4; i++) {
        const int t = t0 + wy + 8 * i;
        float s1s[2];
        int s1i[2];

        // stage 1: top-16 of 256 for BOTH p, interleaved (independent shuffle
        // chains overlap; per-problem op order and tie-breaks unchanged).
        float v0[8], v1[8];
#pragma unroll
        for (int jq = 0; jq < 4; jq++) {
            unsigned lo, hi;
            UNPACK2(lo, hi, acc[0][i][jq]);
            v0[2 * jq + 0] = __uint_as_float(lo);
            v0[2 * jq + 1] = __uint_as_float(hi);
            UNPACK2(lo, hi, acc[1][i][jq]);
            v1[2 * jq + 0] = __uint_as_float(lo);
            v1[2 * jq + 1] = __uint_as_float(hi);
        }
        float os0 = 0.f, os1 = 0.f; int oi0 = 0, oi1 = 0;
#pragma unroll 1
        for (int it = 0; it < 16; it++) {
            float bv0 = -INFINITY, bv1 = -INFINITY;
            int bi0 = 0x7fffffff, bi1 = 0x7fffffff;
#pragma unroll
            for (int s = 0; s < 8; s++) {
                int n = ((s >> 1) << 6) + 2 * tx + (s & 1);
                if (v0[s] > bv0) { bv0 = v0[s]; bi0 = n; }
                if (v1[s] > bv1) { bv1 = v1[s]; bi1 = n; }
            }
#pragma unroll
            for (int o = 16; o; o >>= 1) {
                float ov0 = __shfl_xor_sync(0xffffffffu, bv0, o);
                int   on0 = __shfl_xor_sync(0xffffffffu, bi0, o);
                float ov1 = __shfl_xor_sync(0xffffffffu, bv1, o);
                int   on1 = __shfl_xor_sync(0xffffffffu, bi1, o);
                if (ov0 > bv0 || (ov0 == bv0 && on0 < bi0)) { bv0 = ov0; bi0 = on0; }
                if (ov1 > bv1 || (ov1 == bv1 && on1 < bi1)) { bv1 = ov1; bi1 = on1; }
            }
            if (tx == it) { os0 = bv0; oi0 = bi0; os1 = bv1; oi1 = bi1; }
            if (((bi0 >> 1) & 31) == tx) {
                int sl = ((bi0 >> 6) << 1) | (bi0 & 1);
                v0[sl] = -INFINITY;
            }
            if (((bi1 >> 1) & 31) == tx) {
                int sl = ((bi1 >> 6) << 1) | (bi1 & 1);
                v1[sl] = -INFINITY;
            }
        }
        s1s[0] = os0; s1i[0] = oi0;
        s1s[1] = os1; s1i[1] = oi1;

        // stage 2: top-16 of 50 pruned candidates (lane l: c=l and c=l+32)
        float v2[2]; int cc2[2];
#pragma unroll
        for (int e = 0; e < 2; e++) {
            int c = tx + 32 * e;
            int ii = c_ci[c], jj = c_cj[c];
            float sxv = __shfl_sync(0xffffffffu, s1s[0], ii);
            float syv = __shfl_sync(0xffffffffu, s1s[1], jj);
            v2[e] = (c < 50) ? sxv + syv : -INFINITY;
            cc2[e] = ii * 16 + jj;
        }
        float os = 0.f; int occ = 0;
#pragma unroll 1
        for (int it = 0; it < 16; it++) {
            float bv = -INFINITY; int bcc = 0x7fffffff;
#pragma unroll
            for (int e = 0; e < 2; e++)
                if (v2[e] > bv || (v2[e] == bv && cc2[e] < bcc)) { bv = v2[e]; bcc = cc2[e]; }
#pragma unroll
            for (int o = 16; o; o >>= 1) {
                float ov = __shfl_xor_sync(0xffffffffu, bv, o);
                int oc2 = __shfl_xor_sync(0xffffffffu, bcc, o);
                if (ov > bv || (ov == bv && oc2 < bcc)) { bv = ov; bcc = oc2; }
            }
            if (tx == it) { os = bv; occ = bcc; }
#pragma unroll
            for (int e = 0; e < 2; e++)
                if (cc2[e] == bcc) v2[e] = -INFINITY;
        }

        // softmax over 16 selected (lane 0 = max) + index gather
        float mx = __shfl_sync(0xffffffffu, os, 0);
        float ev = (tx < 16) ? expf(os - mx) : 0.f;
        float sum = ev;
#pragma unroll
        for (int o = 16; o; o >>= 1) sum += __shfl_xor_sync(0xffffffffu, sum, o);
        int ix = __shfl_sync(0xffffffffu, s1i[0], (occ >> 4) & 15);
        int iy = __shfl_sync(0xffffffffu, s1i[1], occ & 15);
        if (tx < 16) {
            int o = (t * HV + h) * KKV + tx;
            g_attn[o] = ev / sum;
            g_vidx[o] = ix * NKV + iy;
        }
    }
}

// ---------------------------------------------------------------------------
// K5: out[t,:] = sum_{m<128} attn[t,m] * values[vidx[t,m], :]
// (at DRAM/L2 bandwidth floor per ncu — unchanged)
// ---------------------------------------------------------------------------
__global__ __launch_bounds__(128) void k5_out(const float* __restrict__ values,
                                              float* __restrict__ out)
{
    __shared__ float sa[128];
    __shared__ int   sv[128];
    const int t = blockIdx.x;
    const int tid = threadIdx.x;
    sa[tid] = g_attn[(size_t)t * 128 + tid];
    sv[tid] = g_vidx[(size_t)t * 128 + tid];
    __syncthreads();

    const float4* V = (const float4*)values;
    float4 acc = make_float4(0.f, 0.f, 0.f, 0.f);
#pragma unroll 8
    for (int m = 0; m < 128; m++) {
        float a = sa[m];
        float4 vv = V[(size_t)sv[m] * 128 + tid];
        acc.x = fmaf(a, vv.x, acc.x);
        acc.y = fmaf(a, vv.y, acc.y);
        acc.z = fmaf(a, vv.z, acc.z);
        acc.w = fmaf(a, vv.w, acc.w);
    }
    ((float4*)out)[(size_t)t * 128 + tid] = acc;
}

// ---------------------------------------------------------------------------
extern "C" void kernel_launch(void* const* d_in, const int* in_sizes, int n_in,
                              void* d_out, int out_size)
{
    const float* x      = (const float*)d_in[0];  // (4,1024,512)
    const float* Wq     = (const float*)d_in[1];  // (2048,512)
    const float* ln_g   = (const float*)d_in[2];  // (128,)
    const float* ln_b   = (const float*)d_in[3];  // (128,)
    const float* keys   = (const float*)d_in[4];  // (8,256,2,128)
    const float* values = (const float*)d_in[5];  // (65536,512)
    float* out = (float*)d_out;                   // (4,1024,512)

    k1_gemm<<<dim3(NTOKS / 64, QDV / 128), 256>>>(x, Wq);
    k2_ln<<<(NTOKS * 16) / 8, 256>>>(ln_g, ln_b);
    k3_fused<<<dim3(NTOKS / 32, HV), 256>>>(keys);
    k5_out<<<NTOKS, 128>>>(values, out);
}